// round 10
// baseline (speedup 1.0000x reference)
#include <cuda_runtime.h>
#include <cstdint>

#define FEAT 128          // output feature dim
#define HF   256          // num_heads * feat_dim (accumulator width)
#define MAX_NODES 50000

// Scratch accumulator: [N, 256] fp32 = 51.2 MB (fits in L2 for atomics)
__device__ float g_acc[(size_t)MAX_NODES * HF];

// ---------------------------------------------------------------------------
// Kernel 0: zero the accumulator (graph replays reuse the scratch buffer)
// ---------------------------------------------------------------------------
__global__ void zero_acc_kernel(int n_f4) {
    float4* p = reinterpret_cast<float4*>(g_acc);
    int i = blockIdx.x * blockDim.x + threadIdx.x;
    int stride = gridDim.x * blockDim.x;
    float4 z = make_float4(0.f, 0.f, 0.f, 0.f);
    for (; i < n_f4; i += stride) p[i] = z;
}

// ---------------------------------------------------------------------------
// Kernel 1: scatter-add per-edge messages into g_acc[dst]
// NOTE: nbrs is int32 ([E,2]) — JAX default config downcasts jnp.int64 to
// int32 (x64 disabled), so reading int64 here was reading two packed ids.
// 64 threads per edge, each thread handles one float4 (16B) of the 1KB row.
// Vectorized red.global.add.v4.f32 (sm_90+) -> 4x fewer atomic ops.
// ---------------------------------------------------------------------------
__global__ void scatter_kernel(const int*   __restrict__ nbrs,
                               const float* __restrict__ scaled_v,
                               int n_edges, int n_nodes) {
    long long g = (long long)blockIdx.x * blockDim.x + threadIdx.x;
    long long e = g >> 6;          // edge index
    int slot = (int)(g & 63);      // which float4 of the 256-float row
    if (e >= n_edges) return;

    int dst = __ldg(nbrs + 2 * e);         // nbrs[e][0], int32
    if ((unsigned)dst >= (unsigned)n_nodes) return;   // crash-proofing

    const float4* sv4 = reinterpret_cast<const float4*>(scaled_v);
    float4 v = __ldg(sv4 + e * 64 + slot);

    float* p = g_acc + (size_t)dst * HF + slot * 4;
    asm volatile("red.global.add.v4.f32 [%0], {%1, %2, %3, %4};"
                 :: "l"(p), "f"(v.x), "f"(v.y), "f"(v.z), "f"(v.w)
                 : "memory");
}

// ---------------------------------------------------------------------------
// Kernel 2: out[n, j] = x_i[n, j] + b[j] + sum_k acc[n, k] * W[j, k]
// W: [128, 256] row-major. Tile: 64 nodes x 128 outputs per block.
// smem: W transposed as [k4=64][j=128] float4, row stride 129 (conflict-free
// STS and LDS); acc tile [64][64] float4.
// Thread (tx = tid&15, ty = tid>>4) computes 4 nodes x 8 outputs,
// j in {tx, tx+16, ..., tx+112} -> consecutive-lane LDS addresses.
// ---------------------------------------------------------------------------
#define TILE_M 64
#define SW_STRIDE 129   // float4 units per k4-row of sW

__global__ void gemm_kernel(const float* __restrict__ x_i,
                            const float* __restrict__ W,
                            const float* __restrict__ b,
                            float*       __restrict__ out,
                            int n_nodes) {
    extern __shared__ float4 smem[];
    float4* sW = smem;                       // [64][SW_STRIDE], uses [k4][j]
    float4* sA = smem + 64 * SW_STRIDE;      // [TILE_M][64]

    const int tid = threadIdx.x;

    // Load W (8192 float4) transposed into smem: sW[k4][j] = W4[j*64 + k4]
    const float4* W4 = reinterpret_cast<const float4*>(W);
    #pragma unroll
    for (int it = 0; it < 32; ++it) {
        int g = tid + it * 256;              // 0..8191, coalesced global read
        int j  = g >> 6;
        int k4 = g & 63;
        sW[k4 * SW_STRIDE + j] = __ldg(W4 + g);
    }

    // Load acc tile [64 nodes][64 f4]
    const int node0 = blockIdx.x * TILE_M;
    const float4* A4 = reinterpret_cast<const float4*>(g_acc);
    #pragma unroll
    for (int it = 0; it < 16; ++it) {
        int g = tid + it * 256;              // 0..4095
        int n  = g >> 6;
        int k4 = g & 63;
        int node = node0 + n;
        sA[g] = (node < n_nodes) ? A4[(size_t)node * 64 + k4]
                                 : make_float4(0.f, 0.f, 0.f, 0.f);
    }
    __syncthreads();

    const int tx = tid & 15;     // output group: j = tx + 16*jj
    const int ty = tid >> 4;     // node group:   n = node0 + ty*4 + i

    float c[4][8];
    #pragma unroll
    for (int i = 0; i < 4; ++i)
        #pragma unroll
        for (int jj = 0; jj < 8; ++jj) c[i][jj] = 0.f;

    #pragma unroll 4
    for (int k4 = 0; k4 < 64; ++k4) {
        float4 a[4];
        #pragma unroll
        for (int i = 0; i < 4; ++i)
            a[i] = sA[(ty * 4 + i) * 64 + k4];
        #pragma unroll
        for (int jj = 0; jj < 8; ++jj) {
            float4 w = sW[k4 * SW_STRIDE + tx + 16 * jj];
            #pragma unroll
            for (int i = 0; i < 4; ++i) {
                c[i][jj] = fmaf(a[i].x, w.x, c[i][jj]);
                c[i][jj] = fmaf(a[i].y, w.y, c[i][jj]);
                c[i][jj] = fmaf(a[i].z, w.z, c[i][jj]);
                c[i][jj] = fmaf(a[i].w, w.w, c[i][jj]);
            }
        }
    }

    // Epilogue: out = x_i + b + c
    #pragma unroll
    for (int i = 0; i < 4; ++i) {
        int node = node0 + ty * 4 + i;
        if (node >= n_nodes) continue;
        #pragma unroll
        for (int jj = 0; jj < 8; ++jj) {
            int j = tx + 16 * jj;
            size_t idx = (size_t)node * FEAT + j;
            out[idx] = __ldg(x_i + idx) + __ldg(b + j) + c[i][jj];
        }
    }
}

// ---------------------------------------------------------------------------
// Launch
// inputs: [0] nbrs int32 [E,2], [1] x_i f32 [N,128], [2] scaled_v f32 [E,256],
//         [3] W f32 [128,256], [4] b f32 [128]
// ---------------------------------------------------------------------------
extern "C" void kernel_launch(void* const* d_in, const int* in_sizes, int n_in,
                              void* d_out, int out_size) {
    const int*   nbrs    = (const int*)d_in[0];
    const float* x_i     = (const float*)d_in[1];
    const float* scaledv = (const float*)d_in[2];
    const float* W       = (const float*)d_in[3];
    const float* b       = (const float*)d_in[4];
    float* out = (float*)d_out;

    const int n_edges = in_sizes[0] / 2;
    const int n_nodes = in_sizes[1] / FEAT;

    // 0. zero accumulator
    int n_f4 = n_nodes * (HF / 4);
    zero_acc_kernel<<<592, 256>>>(n_f4);

    // 1. scatter
    long long total_threads = (long long)n_edges * 64;
    int blocks = (int)((total_threads + 255) / 256);
    scatter_kernel<<<blocks, 256>>>(nbrs, scaledv, n_edges, n_nodes);

    // 2. gemm + residual
    size_t smem_bytes = (64 * SW_STRIDE + TILE_M * 64) * sizeof(float4);
    cudaFuncSetAttribute(gemm_kernel, cudaFuncAttributeMaxDynamicSharedMemorySize,
                         (int)smem_bytes);
    int gblocks = (n_nodes + TILE_M - 1) / TILE_M;
    gemm_kernel<<<gblocks, 256, smem_bytes>>>(x_i, W, b, out, n_nodes);
}